// round 3
// baseline (speedup 1.0000x reference)
#include <cuda_runtime.h>
#include <cstdint>

// Problem constants (fixed by the dataset)
#define BB 32
#define TT 2048
#define KK 512
#define MM 1024          // MAX_MASKED
#define MU 1024          // MAX_UNMASKED
#define K4 (KK / 4)      // 128 float4 per row
#define LN_EPS 1e-5f

// One block per (j, b). 128 threads, each owns one float4 (4 channels).
// Outputs (concatenated in d_out):
//   out0: unmasked_embeddings (B, MU, K)
//   out1: mask_embedding      (B, MM, K)
//   out2: unmasked_positions  (B, MU, K)
__global__ __launch_bounds__(128, 16)
void mae_masking_kernel(
    const float* __restrict__ tok,    // (B, T, K)
    const float* __restrict__ pe,     // (T, K)
    const float* __restrict__ mw,     // (K, 1) -> mask vector over channels
    const float* __restrict__ gamma,  // (K,)
    const float* __restrict__ beta,   // (K,)
    const int*   __restrict__ midx,   // (B, MM)
    const int*   __restrict__ uidx,   // (B, MU)
    const int*   __restrict__ nm,     // (B,)
    const int*   __restrict__ nu,     // (B,)
    float* __restrict__ out)
{
    const int j = blockIdx.x;      // row within batch (0..1023)
    const int b = blockIdx.y;      // batch (0..31)
    const int t = threadIdx.x;     // 0..127, float4 lane

    const bool vu = j < nu[b];
    const bool vm = j < nm[b];
    const int u = uidx[b * MU + j];
    const int m = midx[b * MM + j];

    const float4* __restrict__ pe4  = reinterpret_cast<const float4*>(pe);
    const float4* __restrict__ tok4 = reinterpret_cast<const float4*>(tok);

    const float4 zero = make_float4(0.f, 0.f, 0.f, 0.f);

    // ---- gather paths (predicated) ----
    float4 peu = zero, tk = zero;
    if (vu) {
        peu = pe4[(size_t)u * K4 + t];
        tk  = tok4[((size_t)b * TT + (size_t)u) * K4 + t];
    }

    // ---- mask LayerNorm path (m==0 when invalid -> safe load) ----
    const float4 pem = pe4[(size_t)m * K4 + t];
    const float4 w   = reinterpret_cast<const float4*>(mw)[t];
    float4 x;
    x.x = pem.x + w.x; x.y = pem.y + w.y; x.z = pem.z + w.z; x.w = pem.w + w.w;

    float s  = x.x + x.y + x.z + x.w;
    float ss = x.x * x.x + x.y * x.y + x.z * x.z + x.w * x.w;

    // butterfly warp reduce: every lane ends with the warp total
    #pragma unroll
    for (int o = 16; o > 0; o >>= 1) {
        s  += __shfl_xor_sync(0xffffffffu, s,  o);
        ss += __shfl_xor_sync(0xffffffffu, ss, o);
    }

    __shared__ float sh_s[4], sh_ss[4];
    const int wid = t >> 5, lane = t & 31;
    if (lane == 0) { sh_s[wid] = s; sh_ss[wid] = ss; }
    __syncthreads();

    // every thread combines the 4 warp partials itself (no second barrier)
    const float sum   = sh_s[0]  + sh_s[1]  + sh_s[2]  + sh_s[3];
    const float sumsq = sh_ss[0] + sh_ss[1] + sh_ss[2] + sh_ss[3];
    const float mean  = sum * (1.0f / KK);
    const float var   = sumsq * (1.0f / KK) - mean * mean;
    const float inv   = rsqrtf(var + LN_EPS);

    const float4 g  = reinterpret_cast<const float4*>(gamma)[t];
    const float4 be = reinterpret_cast<const float4*>(beta)[t];
    float4 ln;
    ln.x = (x.x - mean) * inv * g.x + be.x;
    ln.y = (x.y - mean) * inv * g.y + be.y;
    ln.z = (x.z - mean) * inv * g.z + be.z;
    ln.w = (x.w - mean) * inv * g.w + be.w;
    if (!vm) ln = zero;

    // ---- streaming stores (write-once, never re-read: keep L2 for pe/tok) ----
    const size_t row = ((size_t)b * MU + (size_t)j) * K4 + (size_t)t;
    float4* __restrict__ o0 = reinterpret_cast<float4*>(out);
    float4* __restrict__ o1 = o0 + (size_t)BB * MU * K4;
    float4* __restrict__ o2 = o1 + (size_t)BB * MM * K4;

    __stcs(&o0[row], tk);
    __stcs(&o1[row], ln);
    __stcs(&o2[row], peu);
}

extern "C" void kernel_launch(void* const* d_in, const int* in_sizes, int n_in,
                              void* d_out, int out_size)
{
    const float* tok   = (const float*)d_in[0];
    const float* pe    = (const float*)d_in[1];
    const float* mw    = (const float*)d_in[2];
    const float* gamma = (const float*)d_in[3];
    const float* beta  = (const float*)d_in[4];
    const int*   midx  = (const int*)d_in[5];
    const int*   uidx  = (const int*)d_in[6];
    const int*   nm    = (const int*)d_in[7];
    const int*   nu    = (const int*)d_in[8];

    dim3 grid(MU, BB);   // 1024 x 32 blocks (MM == MU)
    dim3 block(128);
    mae_masking_kernel<<<grid, block>>>(tok, pe, mw, gamma, beta,
                                        midx, uidx, nm, nu, (float*)d_out);
}